// round 9
// baseline (speedup 1.0000x reference)
#include <cuda_runtime.h>
#include <cuda_fp16.h>
#include <cstdint>

#define HH   1024
#define BB   64
#define SS   256
#define DD   512
#define G4H  4096

// ---------------- scratch (device globals: allocation-free) ----------------
__device__ float d_gx0[(size_t)SS * BB * G4H];   // [S,B,4H] layer0 input proj
__device__ unsigned d_h1r[3][BB * HH / 2];       // h1 ring (fp16 half2), 3 slots
__device__ unsigned d_h2r[3][BB * HH / 2];       // h2 ring (fp16 half2), 3 slots
__device__ unsigned g_cnt;
__device__ volatile unsigned g_gen;
__device__ int d_gdone[8];                       // per-group phase counters (monotonic)

// ---------------- helpers ----------------
__device__ __forceinline__ unsigned f2tf(float x) {
    unsigned r;
    asm("cvt.rna.tf32.f32 %0, %1;" : "=r"(r) : "f"(x));
    return r;
}

__device__ __forceinline__ void st4(unsigned* p, float4 v) {
    p[0] = f2tf(v.x); p[1] = f2tf(v.y); p[2] = f2tf(v.z); p[3] = f2tf(v.w);
}

__device__ __forceinline__ unsigned pack_h2(float a, float b) {
    __half2 h = __floats2half2_rn(a, b);
    return *(unsigned*)&h;
}

__device__ __forceinline__ void mma8(float d[4], const unsigned a[4], const unsigned b[2]) {
    asm volatile(
        "mma.sync.aligned.m16n8k8.row.col.f32.tf32.tf32.f32 "
        "{%0,%1,%2,%3},{%4,%5,%6,%7},{%8,%9},{%0,%1,%2,%3};\n"
        : "+f"(d[0]), "+f"(d[1]), "+f"(d[2]), "+f"(d[3])
        : "r"(a[0]), "r"(a[1]), "r"(a[2]), "r"(a[3]), "r"(b[0]), "r"(b[1]));
}

__device__ __forceinline__ void mma16h(float d[4], const unsigned a[4], const unsigned b[2]) {
    asm volatile(
        "mma.sync.aligned.m16n8k16.row.col.f32.f16.f16.f32 "
        "{%0,%1,%2,%3},{%4,%5,%6,%7},{%8,%9},{%0,%1,%2,%3};\n"
        : "+f"(d[0]), "+f"(d[1]), "+f"(d[2]), "+f"(d[3])
        : "r"(a[0]), "r"(a[1]), "r"(a[2]), "r"(a[3]), "r"(b[0]), "r"(b[1]));
}

__device__ __forceinline__ void ldsm_x4(unsigned (&r)[4], unsigned addr) {
    asm volatile(
        "ldmatrix.sync.aligned.m8n8.x4.shared.b16 {%0,%1,%2,%3}, [%4];\n"
        : "=r"(r[0]), "=r"(r[1]), "=r"(r[2]), "=r"(r[3]) : "r"(addr));
}

#define NBAR() asm volatile("bar.sync 1, 256;" ::: "memory")

__device__ __forceinline__ void grid_barrier(unsigned nct) {
    __threadfence();
    __syncthreads();
    if (threadIdx.x == 0) {
        const unsigned g = g_gen;
        if (atomicAdd(&g_cnt, 1u) == nct - 1u) {
            g_cnt = 0u;
            __threadfence();
            g_gen = g + 1u;
        } else {
            while (g_gen == g) __nanosleep(20);
            __threadfence();
        }
    }
    __syncthreads();
}

// ---------------- input-projection GEMM (tf32, layer0 only) ----------------
__global__ __launch_bounds__(256) void proj_kernel(
    const float* __restrict__ A, const float* __restrict__ W,
    const float* __restrict__ bias1, const float* __restrict__ bias2,
    float* __restrict__ C, int K) {
    __shared__ unsigned As[2][64][20];
    __shared__ unsigned Bs[2][128][20];

    const int tid = threadIdx.x;
    const int lane = tid & 31, warp = tid >> 5;
    const int wm = warp >> 2, wn = warp & 3;
    const int g4 = lane >> 2, t4 = lane & 3;
    const int m0 = blockIdx.y * 64;
    const int n0 = blockIdx.x * 128;

    float acc[2][4][4];
#pragma unroll
    for (int a = 0; a < 2; a++)
#pragma unroll
        for (int b = 0; b < 4; b++)
#pragma unroll
            for (int c = 0; c < 4; c++) acc[a][b][c] = 0.f;

    const int ar = tid >> 2;
    const int ac = (tid & 3) << 2;
    const float* Ap  = A + (size_t)(m0 + ar) * K + ac;
    const float* Bp0 = W + (size_t)(n0 + ar) * K + ac;
    const float* Bp1 = W + (size_t)(n0 + ar + 64) * K + ac;
    const int KT = K >> 4;

    float4 av  = *(const float4*)Ap;
    float4 bv0 = *(const float4*)Bp0;
    float4 bv1 = *(const float4*)Bp1;
    st4(&As[0][ar][ac], av);
    st4(&Bs[0][ar][ac], bv0);
    st4(&Bs[0][ar + 64][ac], bv1);
    __syncthreads();

    int buf = 0;
    for (int kt = 0; kt < KT; kt++) {
        const int kn = (kt + 1) << 4;
        if (kt + 1 < KT) {
            av  = *(const float4*)(Ap + kn);
            bv0 = *(const float4*)(Bp0 + kn);
            bv1 = *(const float4*)(Bp1 + kn);
        }
#pragma unroll
        for (int kk = 0; kk < 2; kk++) {
            const int k8 = kk * 8;
            unsigned af[2][4], bf[4][2];
#pragma unroll
            for (int im = 0; im < 2; im++) {
                const int r = wm * 32 + im * 16;
                af[im][0] = As[buf][r + g4][k8 + t4];
                af[im][1] = As[buf][r + 8 + g4][k8 + t4];
                af[im][2] = As[buf][r + g4][k8 + 4 + t4];
                af[im][3] = As[buf][r + 8 + g4][k8 + 4 + t4];
            }
#pragma unroll
            for (int in = 0; in < 4; in++) {
                const int c = wn * 32 + in * 8;
                bf[in][0] = Bs[buf][c + g4][k8 + t4];
                bf[in][1] = Bs[buf][c + g4][k8 + 4 + t4];
            }
#pragma unroll
            for (int im = 0; im < 2; im++)
#pragma unroll
                for (int in = 0; in < 4; in++)
                    mma8(acc[im][in], af[im], bf[in]);
        }
        if (kt + 1 < KT) {
            st4(&As[buf ^ 1][ar][ac], av);
            st4(&Bs[buf ^ 1][ar][ac], bv0);
            st4(&Bs[buf ^ 1][ar + 64][ac], bv1);
        }
        __syncthreads();
        buf ^= 1;
    }

#pragma unroll
    for (int im = 0; im < 2; im++) {
#pragma unroll
        for (int in = 0; in < 4; in++) {
            const int col = n0 + wn * 32 + in * 8 + (t4 << 1);
            const float bb0 = bias1[col] + bias2[col];
            const float bb1 = bias1[col + 1] + bias2[col + 1];
            const int r0 = m0 + wm * 32 + im * 16 + g4;
            const int r1 = r0 + 8;
            const size_t o0 = ((size_t)((r0 & (SS - 1)) * BB + (r0 >> 8))) * G4H + col;
            const size_t o1 = ((size_t)((r1 & (SS - 1)) * BB + (r1 >> 8))) * G4H + col;
            *(float2*)(C + o0) = make_float2(acc[im][in][0] + bb0, acc[im][in][1] + bb1);
            *(float2*)(C + o1) = make_float2(acc[im][in][2] + bb0, acc[im][in][3] + bb1);
        }
    }
}

// ---------------- reset kernel (per-launch counter reset) ------------------
__global__ void reset_kernel() {
    if (threadIdx.x < 8) d_gdone[threadIdx.x] = 0;
}

// ---------------- fused 2-layer persistent recurrent kernel ----------------
// 128 CTAs x 288 threads (8 compute warps + 1 free-running monitor warp).
// CTA owns 8 hidden units (jb) of BOTH layers. Phase t (0..256):
//   layer0: h1[t]   = cell( gx0[t] + W_hh0 @ h1[t-1] )                (t<256)
//   layer1: h2[t-1] = cell( [W_ih1;W_hh1] @ [h1[t-1]; h2[t-2]] + b )  (t>0)
// Chunk nc's prefetch gates on group nc&7 (16 CTAs) having finished phase
// t-1 (monotonic d_gdone[8], published to smem vrdy by the monitor warp).
// Gates for all 8 groups complete by chunk 5 -> up to ~6 chunks of compute
// overlap the slowest producer's tail. 3-slot rings make WAR safe (skew<1
// phase is enforced by the gates themselves). No per-phase grid barrier.
#define WS0_STRIDE 512
#define WS1_STRIDE 1024
#define OFF_WS1   (32 * WS0_STRIDE)                 // 16384
#define OFF_AS    (OFF_WS1 + 32 * WS1_STRIDE)       // 49152
#define AS_STRIDE 68
#define AS_BUF    (64 * AS_STRIDE)                  // 4352
#define OFF_READY (OFF_AS + 2 * AS_BUF)             // 57856
#define SMEM_WORDS (OFF_READY + 8)                  // 57864
#define REC_SMEM_BYTES (SMEM_WORDS * 4)             // 231456 (< 231936 proven)
#define GSM_SEC   (64 * 34)

__device__ __forceinline__ void prefetch_chunk(const unsigned* src0, int chunkk,
                                               unsigned* dst, int tid) {
#pragma unroll
    for (int it = 0; it < 4; it++) {
        const int s = tid + it * 256;
        const int row = s >> 4;
        const int c4 = (s & 15) << 2;
        const unsigned* src = src0 + (size_t)row * (HH / 2) + chunkk * 64 + c4;
        unsigned d = (unsigned)__cvta_generic_to_shared(dst + row * AS_STRIDE + c4);
        asm volatile("cp.async.cg.shared.global [%0], [%1], 16;\n" :: "r"(d), "l"(src));
    }
    asm volatile("cp.async.commit_group;\n");
}

__global__ __launch_bounds__(288) void fused_rec(
    const float* __restrict__ gx, const float* __restrict__ Whh0,
    const float* __restrict__ Wih1, const float* __restrict__ Whh1,
    const float* __restrict__ bih1, const float* __restrict__ bhh1,
    float* __restrict__ out) {
    extern __shared__ unsigned smu[];
    unsigned* Ws0 = smu;
    unsigned* Ws1 = smu + OFF_WS1;
    unsigned* Asm = smu + OFF_AS;
    float* gsm = (float*)(smu + OFF_AS);   // union: valid after GEMM of a phase
    volatile int* vrdy = (volatile int*)(smu + OFF_READY);

    const int tid = threadIdx.x;
    const int lane = tid & 31, warp = tid >> 5;
    const int wk = warp >> 2;
    const int wm = (warp >> 1) & 1;
    const int wn = warp & 1;
    const int jb = blockIdx.x << 3;
    const int grp = blockIdx.x >> 4;
    const unsigned nct = gridDim.x;

    if (tid < 8) vrdy[tid] = -1;

    // --- one-time init (compute warps): W slabs (swizzled), zero rings ---
    if (warp < 8) {
        for (int idx = tid; idx < 32 * 512; idx += 256) {
            const int v = idx >> 9, kh = idx & 511;
            const int grow = (v >> 3) * HH + jb + (v & 7);
            const float2 w2 = *(const float2*)(Whh0 + (size_t)grow * HH + 2 * kh);
            Ws0[v * WS0_STRIDE + (kh ^ ((v & 7) << 2))] = pack_h2(w2.x, w2.y);
        }
        for (int idx = tid; idx < 32 * 1024; idx += 256) {
            const int v = idx >> 10, kh = idx & 1023;
            const int grow = (v >> 3) * HH + jb + (v & 7);
            float2 w2;
            if (kh < 512) w2 = *(const float2*)(Wih1 + (size_t)grow * HH + 2 * kh);
            else          w2 = *(const float2*)(Whh1 + (size_t)grow * HH + 2 * (kh - 512));
            Ws1[v * WS1_STRIDE + (kh ^ ((v & 7) << 2))] = pack_h2(w2.x, w2.y);
        }
        {
            const int b = tid >> 2, q = tid & 3;
#pragma unroll
            for (int s = 0; s < 3; s++) {
                d_h1r[s][b * (HH / 2) + (jb >> 1) + q] = 0u;
                d_h2r[s][b * (HH / 2) + (jb >> 1) + q] = 0u;
            }
        }
    }
    grid_barrier(nct);   // one-time: rings + weights + vrdy init visible

    // ============ monitor warp: free-running, no block syncs ============
    if (warp >= 8) {
        if (lane < 8) {
#pragma unroll 1
            for (int t = 0; t <= SS; t++) {
                const int tgt = 16 * t;
                while (__ldcg(&d_gdone[lane]) < tgt) __nanosleep(30);
                __threadfence();
                vrdy[lane] = t;
            }
        }
        return;
    }

    // =================== compute warps (0-7) ===================
    const int cbase = tid >> 2;
    const int u0 = (tid & 3) << 1;

    float bs[8];
#pragma unroll
    for (int g = 0; g < 4; g++) {
        bs[2 * g]     = bih1[g * HH + jb + u0]     + bhh1[g * HH + jb + u0];
        bs[2 * g + 1] = bih1[g * HH + jb + u0 + 1] + bhh1[g * HH + jb + u0 + 1];
    }

    const unsigned base_u = (unsigned)__cvta_generic_to_shared(smu);
    const int r8   = lane & 7;
    const int sel8 = (lane & 8) ? 8 : 0;
    const int selk = (lane & 16) ? 4 : 0;
    const int szB  = selk ^ (r8 << 2);
    const unsigned offA0 = (unsigned)((wm * 32 + r8 + sel8) * AS_STRIDE + selk);
    const unsigned offA1 = offA0 + 16 * AS_STRIDE;
    const unsigned abase[2] = { base_u + OFF_AS * 4,
                                base_u + (OFF_AS + AS_BUF) * 4 };
    const unsigned b1base = base_u + (OFF_WS1 + (wn * 16 + r8 + sel8) * WS1_STRIDE) * 4;
    const unsigned b0base = base_u + ((wn * 16 + r8 + sel8) * WS0_STRIDE) * 4;

    float c0a = 0.f, c0b = 0.f;
    float c1a = 0.f, c1b = 0.f;

#pragma unroll 1
    for (int t = 0; t <= SS; t++) {
        // ring: h1[t]->t%3, h1[t-1]->(t+2)%3; h2[t-1]->(t+2)%3, h2[t-2]->(t+1)%3
        const unsigned* h1p = d_h1r[(t + 2) % 3];
        unsigned* h1n = d_h1r[t % 3];
        const unsigned* h2p = d_h2r[(t + 1) % 3];
        unsigned* h2n = d_h2r[(t + 2) % 3];

        float2 gxi, gxf, gxg, gxo;
        if (t < SS) {
            const float* gp = gx + (size_t)t * (BB * G4H) + (size_t)cbase * G4H + jb + u0;
            gxi = *(const float2*)(gp);
            gxf = *(const float2*)(gp + HH);
            gxg = *(const float2*)(gp + 2 * HH);
            gxo = *(const float2*)(gp + 3 * HH);
        }

        float acc[2][2][2][4];
#pragma unroll
        for (int L = 0; L < 2; L++)
#pragma unroll
            for (int a = 0; a < 2; a++)
#pragma unroll
                for (int b = 0; b < 2; b++)
#pragma unroll
                    for (int c = 0; c < 4; c++) acc[L][a][b][c] = 0.f;

        while (vrdy[0] < t) __nanosleep(20);
        prefetch_chunk(h1p, 0, Asm, tid);
        while (vrdy[1] < t) __nanosleep(20);
        prefetch_chunk(h1p, 1, Asm + AS_BUF, tid);

#pragma unroll 1
        for (int c = 0; c < 16; c++) {
            if (c < 15) { asm volatile("cp.async.wait_group 1;\n"); }
            else        { asm volatile("cp.async.wait_group 0;\n"); }
            NBAR();
            const unsigned ab = abase[c & 1];
            const int kwarp = c * 64 + wk * 32;
#pragma unroll
            for (int kk = 0; kk < 4; kk++) {
                const int ks = wk * 32 + kk * 8;
                const int kw = kwarp + kk * 8;
                unsigned af0[4], af1[4];
                ldsm_x4(af0, ab + ((offA0 + ks) << 2));
                ldsm_x4(af1, ab + ((offA1 + ks) << 2));
                {
                    unsigned bq[4];
                    ldsm_x4(bq, b1base + ((unsigned)(kw ^ szB) << 2));
                    unsigned bfa[2] = { bq[0], bq[2] };
                    unsigned bfb[2] = { bq[1], bq[3] };
                    mma16h(acc[1][0][0], af0, bfa);
                    mma16h(acc[1][0][1], af0, bfb);
                    mma16h(acc[1][1][0], af1, bfa);
                    mma16h(acc[1][1][1], af1, bfb);
                }
                if (c < 8) {
                    unsigned bq[4];
                    ldsm_x4(bq, b0base + ((unsigned)(kw ^ szB) << 2));
                    unsigned bfa[2] = { bq[0], bq[2] };
                    unsigned bfb[2] = { bq[1], bq[3] };
                    mma16h(acc[0][0][0], af0, bfa);
                    mma16h(acc[0][0][1], af0, bfb);
                    mma16h(acc[0][1][0], af1, bfa);
                    mma16h(acc[0][1][1], af1, bfb);
                }
            }
            NBAR();
            if (c + 2 < 16) {
                const int nc = c + 2;
                if (nc < 8) { while (vrdy[nc] < t) __nanosleep(20); }
                prefetch_chunk(nc < 8 ? h1p : h2p, nc & 7, Asm + (c & 1) * AS_BUF, tid);
            }
        }

        // dump partials into gsm (unioned over As): section = layer*2 + wk
        {
            const int g4 = lane >> 2, t4 = lane & 3;
#pragma unroll
            for (int L = 0; L < 2; L++) {
                float* gb = gsm + (L * 2 + wk) * GSM_SEC;
#pragma unroll
                for (int im = 0; im < 2; im++) {
#pragma unroll
                    for (int in = 0; in < 2; in++) {
                        const int row = wm * 32 + im * 16 + g4;
                        const int col = wn * 16 + in * 8 + (t4 << 1);
                        *(float2*)(gb + row * 34 + col) =
                            make_float2(acc[L][im][in][0], acc[L][im][in][1]);
                        *(float2*)(gb + (row + 8) * 34 + col) =
                            make_float2(acc[L][im][in][2], acc[L][im][in][3]);
                    }
                }
            }
        }
        NBAR();

        // ---- layer0 cell update ----
        if (t < SS) {
            const float* s0 = gsm + cbase * 34;
            const float* s1 = gsm + GSM_SEC + cbase * 34;
            const float gi0 = s0[u0]      + s1[u0]      + gxi.x;
            const float gi1 = s0[u0 + 1]  + s1[u0 + 1]  + gxi.y;
            const float gf0 = s0[8 + u0]  + s1[8 + u0]  + gxf.x;
            const float gf1 = s0[9 + u0]  + s1[9 + u0]  + gxf.y;
            const float gg0 = s0[16 + u0] + s1[16 + u0] + gxg.x;
            const float gg1 = s0[17 + u0] + s1[17 + u0] + gxg.y;
            const float go0 = s0[24 + u0] + s1[24 + u0] + gxo.x;
            const float go1 = s0[25 + u0] + s1[25 + u0] + gxo.y;
            const float i0 = 1.f / (1.f + expf(-gi0));
            const float i1 = 1.f / (1.f + expf(-gi1));
            const float f0 = 1.f / (1.f + expf(-gf0));
            const float f1 = 1.f / (1.f + expf(-gf1));
            const float z0 = tanhf(gg0);
            const float z1 = tanhf(gg1);
            const float o0 = 1.f / (1.f + expf(-go0));
            const float o1 = 1.f / (1.f + expf(-go1));
            c0a = f0 * c0a + i0 * z0;
            c0b = f1 * c0b + i1 * z1;
            const float h0 = o0 * tanhf(c0a);
            const float h1 = o1 * tanhf(c0b);
            h1n[cbase * (HH / 2) + ((jb + u0) >> 1)] = pack_h2(h0, h1);
        }

        // ---- layer1 cell update (computes h2[t-1]) ----
        if (t > 0) {
            const float* s2 = gsm + 2 * GSM_SEC + cbase * 34;
            const float* s3 = gsm + 3 * GSM_SEC + cbase * 34;
            const float gi0 = s2[u0]      + s3[u0]      + bs[0];
            const float gi1 = s2[u0 + 1]  + s3[u0 + 1]  + bs[1];
            const float gf0 = s2[8 + u0]  + s3[8 + u0]  + bs[2];
            const float gf1 = s2[9 + u0]  + s3[9 + u0]  + bs[3];
            const float gg0 = s2[16 + u0] + s3[16 + u0] + bs[4];
            const float gg1 = s2[17 + u0] + s3[17 + u0] + bs[5];
            const float go0 = s2[24 + u0] + s3[24 + u0] + bs[6];
            const float go1 = s2[25 + u0] + s3[25 + u0] + bs[7];
            const float i0 = 1.f / (1.f + expf(-gi0));
            const float i1 = 1.f / (1.f + expf(-gi1));
            const float f0 = 1.f / (1.f + expf(-gf0));
            const float f1 = 1.f / (1.f + expf(-gf1));
            const float z0 = tanhf(gg0);
            const float z1 = tanhf(gg1);
            const float o0 = 1.f / (1.f + expf(-go0));
            const float o1 = 1.f / (1.f + expf(-go1));
            c1a = f0 * c1a + i0 * z0;
            c1b = f1 * c1b + i1 * z1;
            const float h0 = o0 * tanhf(c1a);
            const float h1 = o1 * tanhf(c1b);
            h2n[cbase * (HH / 2) + ((jb + u0) >> 1)] = pack_h2(h0, h1);
            const float r0 = h0 > 0.f ? h0 : 0.f;
            const float r1 = h1 > 0.f ? h1 : 0.f;
            *(float2*)(out + (size_t)cbase * (SS * HH) + (size_t)(t - 1) * HH + jb + u0) =
                make_float2(1.f / (1.f + expf(-r0)), 1.f / (1.f + expf(-r1)));
        }

        NBAR();              // all gsm reads + h writes done before release
        if (tid == 0) {
            __threadfence();
            atomicAdd(&d_gdone[grp], 1);
        }
    }
}

// ---------------- launch ----------------
extern "C" void kernel_launch(void* const* d_in, const int* in_sizes, int n_in,
                              void* d_out, int out_size) {
    const float* x    = (const float*)d_in[0];
    const float* Wih0 = (const float*)d_in[1];
    const float* Whh0 = (const float*)d_in[2];
    const float* bih0 = (const float*)d_in[3];
    const float* bhh0 = (const float*)d_in[4];
    const float* Wih1 = (const float*)d_in[5];
    const float* Whh1 = (const float*)d_in[6];
    const float* bih1 = (const float*)d_in[7];
    const float* bhh1 = (const float*)d_in[8];
    float* out = (float*)d_out;

    float* gx0;
    cudaGetSymbolAddress((void**)&gx0, d_gx0);

    cudaFuncSetAttribute(fused_rec,
                         cudaFuncAttributeMaxDynamicSharedMemorySize, REC_SMEM_BYTES);

    dim3 gridP(G4H / 128, (BB * SS) / 64);   // (32, 256)

    reset_kernel<<<1, 32>>>();
    proj_kernel<<<gridP, 256>>>(x, Wih0, bih0, bhh0, gx0, DD);
    fused_rec<<<128, 288, REC_SMEM_BYTES>>>(gx0, Whh0, Wih1, Whh1, bih1, bhh1, out);
}